// round 2
// baseline (speedup 1.0000x reference)
#include <cuda_runtime.h>

#define GRID_N   7
#define NB       2
#define NC       20
#define IS       8
#define DCH      30
#define L_BOX    5.0f
#define L_NEG    0.5f

#define TPB      256
#define MAX_BLOCKS 4096

__device__ double g_partials[MAX_BLOCKS];

__device__ __forceinline__ float bce_f(float x, float t) {
    // max(x,0) - x*t + log1p(exp(-|x|))
    return fmaxf(x, 0.0f) - x * t + log1pf(expf(-fabsf(x)));
}

__device__ __forceinline__ float box_loss_f(const float* pb, const float* gb) {
    float dx = pb[0] - gb[0];
    float dy = pb[1] - gb[1];
    float sw = sqrtf(fabsf(pb[2])) - sqrtf(gb[2]);
    float sh = sqrtf(fabsf(pb[3])) - sqrtf(gb[3]);
    return dx * dx + dy * dy + sw * sw + sh * sh;
}

__global__ void __launch_bounds__(TPB)
yolo_loss_kernel(const float* __restrict__ p, const float* __restrict__ g, int ncells) {
    int idx = blockIdx.x * TPB + threadIdx.x;
    float acc = 0.0f;

    if (idx < ncells) {
        const float2* p2 = reinterpret_cast<const float2*>(p + (size_t)idx * DCH);
        const float2* g2 = reinterpret_cast<const float2*>(g + (size_t)idx * DCH);
        float pv[DCH], gv[DCH];
        #pragma unroll
        for (int i = 0; i < DCH / 2; i++) {
            float2 a = p2[i]; pv[2 * i] = a.x; pv[2 * i + 1] = a.y;
            float2 b = g2[i]; gv[2 * i] = b.x; gv[2 * i + 1] = b.y;
        }

        float conf_g = gv[IS];
        if (conf_g > 0.0f) {
            // ---- classification term ----
            float cls = 0.0f;
            #pragma unroll
            for (int i = 0; i < NC; i++)
                cls += bce_f(pv[NB * 5 + i], gv[NB * 5 + i]);

            // ---- cell coordinates: cr = (col, row) ----
            int cell = idx % (GRID_N * GRID_N);
            float col = (float)(cell % GRID_N);
            float row = (float)(cell / GRID_N);

            // ---- box offsets ----
            float poff[NB][4], gbox[NB][4];
            #pragma unroll
            for (int b = 0; b < NB; b++) {
                poff[b][0] = 1.0f / (1.0f + expf(-pv[4 * b + 0]));
                poff[b][1] = 1.0f / (1.0f + expf(-pv[4 * b + 1]));
                poff[b][2] = pv[4 * b + 2];
                poff[b][3] = pv[4 * b + 3];
                gbox[b][0] = gv[4 * b + 0];
                gbox[b][1] = gv[4 * b + 1];
                gbox[b][2] = gv[4 * b + 2];
                gbox[b][3] = gv[4 * b + 3];
            }

            // ---- ltrb boxes in image coords ----
            float pl[NB][4], gl[NB][4];
            #pragma unroll
            for (int b = 0; b < NB; b++) {
                float cx = (poff[b][0] + col) * (1.0f / GRID_N);
                float cy = (poff[b][1] + row) * (1.0f / GRID_N);
                float w  = poff[b][2], h = poff[b][3];
                pl[b][0] = cx - w * 0.5f; pl[b][1] = cy - h * 0.5f;
                pl[b][2] = cx + w * 0.5f; pl[b][3] = cy + h * 0.5f;
                float gx = (gbox[b][0] + col) * (1.0f / GRID_N);
                float gy = (gbox[b][1] + row) * (1.0f / GRID_N);
                float gw = gbox[b][2], gh = gbox[b][3];
                gl[b][0] = gx - gw * 0.5f; gl[b][1] = gy - gh * 0.5f;
                gl[b][2] = gx + gw * 0.5f; gl[b][3] = gy + gh * 0.5f;
            }

            // ---- 2x2 IoU matrix: iou[pi][gi] ----
            float iou[NB][NB];
            #pragma unroll
            for (int pi = 0; pi < NB; pi++) {
                #pragma unroll
                for (int gi = 0; gi < NB; gi++) {
                    float ltx = fmaxf(pl[pi][0], gl[gi][0]);
                    float lty = fmaxf(pl[pi][1], gl[gi][1]);
                    float rbx = fminf(pl[pi][2], gl[gi][2]);
                    float rby = fminf(pl[pi][3], gl[gi][3]);
                    float wx = fmaxf(rbx - ltx, 0.0f);
                    float wy = fmaxf(rby - lty, 0.0f);
                    float inter = wx * wy;
                    float aa = (pl[pi][2] - pl[pi][0]) * (pl[pi][3] - pl[pi][1]);
                    float ab = (gl[gi][2] - gl[gi][0]) * (gl[gi][3] - gl[gi][1]);
                    iou[pi][gi] = inter / (aa + ab - inter + 1e-7f);
                }
            }

            // argmax over pi (first index wins ties, matching jnp.argmax)
            int ind0 = (iou[1][0] > iou[0][0]) ? 1 : 0;
            int ind1 = (iou[1][1] > iou[0][1]) ? 1 : 0;

            bool same_g = (gbox[0][0] == gbox[1][0]) && (gbox[0][1] == gbox[1][1]) &&
                          (gbox[0][2] == gbox[1][2]) && (gbox[0][3] == gbox[1][3]);
            bool same_ind = (ind0 == ind1);

            float box_cell;
            if (same_g) {
                box_cell = box_loss_f(poff[ind0], gbox[0]);
            } else if (same_ind) {
                box_cell = box_loss_f(poff[0], gbox[0]) + box_loss_f(poff[1], gbox[1]);
            } else {
                box_cell = box_loss_f(poff[ind0], gbox[0]) + box_loss_f(poff[ind1], gbox[1]);
            }

            float pc0 = pv[IS], pc1 = pv[IS + 1];
            float conf_cell = same_g ? bce_f(ind1 ? pc1 : pc0, 1.0f)
                                     : (bce_f(pc0, 1.0f) + bce_f(pc1, 1.0f));

            acc = L_BOX * box_cell + conf_cell + cls;
        } else {
            // negative cell: 0.5 * (bce(pc0,0)+bce(pc1,0))
            float negc = bce_f(pv[IS], 0.0f) + bce_f(pv[IS + 1], 0.0f);
            acc = L_NEG * negc;
        }
    }

    // ---- deterministic block reduction ----
    #pragma unroll
    for (int o = 16; o > 0; o >>= 1)
        acc += __shfl_down_sync(0xffffffffu, acc, o);

    __shared__ float warp_sums[TPB / 32];
    int lane = threadIdx.x & 31;
    int wid  = threadIdx.x >> 5;
    if (lane == 0) warp_sums[wid] = acc;
    __syncthreads();

    if (wid == 0) {
        float v = (lane < TPB / 32) ? warp_sums[lane] : 0.0f;
        #pragma unroll
        for (int o = 4; o > 0; o >>= 1)
            v += __shfl_down_sync(0xffffffffu, v, o);
        if (lane == 0) g_partials[blockIdx.x] = (double)v;
    }
}

__global__ void __launch_bounds__(256)
yolo_finalize_kernel(float* __restrict__ out, int nblocks, float inv_nb) {
    __shared__ double sh[256];
    double s = 0.0;
    for (int i = threadIdx.x; i < nblocks; i += 256)
        s += g_partials[i];
    sh[threadIdx.x] = s;
    __syncthreads();
    for (int stride = 128; stride > 0; stride >>= 1) {
        if (threadIdx.x < stride) sh[threadIdx.x] += sh[threadIdx.x + stride];
        __syncthreads();
    }
    if (threadIdx.x == 0) out[0] = (float)(sh[0] * (double)inv_nb);
}

extern "C" void kernel_launch(void* const* d_in, const int* in_sizes, int n_in,
                              void* d_out, int out_size) {
    const float* p = (const float*)d_in[0];
    const float* g = (const float*)d_in[1];
    float* out = (float*)d_out;

    int ncells = in_sizes[0] / DCH;                 // B * 49
    int batch  = ncells / (GRID_N * GRID_N);        // B
    int nblocks = (ncells + TPB - 1) / TPB;

    yolo_loss_kernel<<<nblocks, TPB>>>(p, g, ncells);
    yolo_finalize_kernel<<<1, 256>>>(out, nblocks, 1.0f / (float)batch);
}

// round 3
// speedup vs baseline: 1.0213x; 1.0213x over previous
#include <cuda_runtime.h>

#define GRID_N   7
#define NB       2
#define NC       20
#define IS       8
#define DCH      30
#define L_BOX    5.0f
#define L_NEG    0.5f

#define TPB      128          // threads per block == cells per block
#define MAX_BLOCKS 8192

__device__ double g_partials[MAX_BLOCKS];
__device__ unsigned int g_count = 0;

__device__ __forceinline__ float bce_f(float x, float t) {
    // max(x,0) - x*t + log1p(exp(-|x|)), fast-math version
    return fmaxf(x, 0.0f) - x * t + __logf(1.0f + __expf(-fabsf(x)));
}

__device__ __forceinline__ float box_loss_f(const float* pb, const float* gb) {
    float dx = pb[0] - gb[0];
    float dy = pb[1] - gb[1];
    float sw = sqrtf(fabsf(pb[2])) - sqrtf(gb[2]);
    float sh = sqrtf(fabsf(pb[3])) - sqrtf(gb[3]);
    return dx * dx + dy * dy + sw * sw + sh * sh;
}

__global__ void __launch_bounds__(TPB)
yolo_loss_kernel(const float* __restrict__ p, const float* __restrict__ g,
                 int ncells, float* __restrict__ out, float inv_nb) {
    __shared__ float sp[TPB * DCH];
    __shared__ float sg[TPB * DCH];

    const int tid = threadIdx.x;
    const int blockBase = blockIdx.x * TPB;

    // ---- stage this block's slab into smem with coalesced float4 loads ----
    if (blockBase + TPB <= ncells) {
        const float4* p4 = reinterpret_cast<const float4*>(p + (size_t)blockBase * DCH);
        const float4* g4 = reinterpret_cast<const float4*>(g + (size_t)blockBase * DCH);
        float4* sp4 = reinterpret_cast<float4*>(sp);
        float4* sg4 = reinterpret_cast<float4*>(sg);
        const int n4 = TPB * DCH / 4;   // 960
        #pragma unroll
        for (int i = tid; i < n4; i += TPB) {
            sp4[i] = p4[i];
            sg4[i] = g4[i];
        }
    } else {
        int nrem = (ncells - blockBase) * DCH;
        const float* pb = p + (size_t)blockBase * DCH;
        const float* gb = g + (size_t)blockBase * DCH;
        for (int i = tid; i < nrem; i += TPB) {
            sp[i] = pb[i];
            sg[i] = gb[i];
        }
    }
    __syncthreads();

    const int idx = blockBase + tid;
    float acc = 0.0f;

    if (idx < ncells) {
        const float* pv = sp + tid * DCH;
        const float* gv = sg + tid * DCH;

        float conf_g = gv[IS];
        if (conf_g > 0.0f) {
            // ---- classification term ----
            float cls = 0.0f;
            #pragma unroll
            for (int i = 0; i < NC; i++)
                cls += bce_f(pv[NB * 5 + i], gv[NB * 5 + i]);

            // ---- cell coordinates: cr = (col, row) ----
            int cell = idx % (GRID_N * GRID_N);
            float col = (float)(cell % GRID_N);
            float row = (float)(cell / GRID_N);

            // ---- box offsets ----
            float poff[NB][4], gbox[NB][4];
            #pragma unroll
            for (int b = 0; b < NB; b++) {
                poff[b][0] = __fdividef(1.0f, 1.0f + __expf(-pv[4 * b + 0]));
                poff[b][1] = __fdividef(1.0f, 1.0f + __expf(-pv[4 * b + 1]));
                poff[b][2] = pv[4 * b + 2];
                poff[b][3] = pv[4 * b + 3];
                gbox[b][0] = gv[4 * b + 0];
                gbox[b][1] = gv[4 * b + 1];
                gbox[b][2] = gv[4 * b + 2];
                gbox[b][3] = gv[4 * b + 3];
            }

            // ---- ltrb boxes in image coords ----
            float pl[NB][4], gl[NB][4];
            #pragma unroll
            for (int b = 0; b < NB; b++) {
                float cx = (poff[b][0] + col) * (1.0f / GRID_N);
                float cy = (poff[b][1] + row) * (1.0f / GRID_N);
                float w  = poff[b][2], h = poff[b][3];
                pl[b][0] = cx - w * 0.5f; pl[b][1] = cy - h * 0.5f;
                pl[b][2] = cx + w * 0.5f; pl[b][3] = cy + h * 0.5f;
                float gx = (gbox[b][0] + col) * (1.0f / GRID_N);
                float gy = (gbox[b][1] + row) * (1.0f / GRID_N);
                float gw = gbox[b][2], gh = gbox[b][3];
                gl[b][0] = gx - gw * 0.5f; gl[b][1] = gy - gh * 0.5f;
                gl[b][2] = gx + gw * 0.5f; gl[b][3] = gy + gh * 0.5f;
            }

            // ---- 2x2 IoU matrix: iou[pi][gi] ----
            float iou[NB][NB];
            #pragma unroll
            for (int pi = 0; pi < NB; pi++) {
                #pragma unroll
                for (int gi = 0; gi < NB; gi++) {
                    float ltx = fmaxf(pl[pi][0], gl[gi][0]);
                    float lty = fmaxf(pl[pi][1], gl[gi][1]);
                    float rbx = fminf(pl[pi][2], gl[gi][2]);
                    float rby = fminf(pl[pi][3], gl[gi][3]);
                    float wx = fmaxf(rbx - ltx, 0.0f);
                    float wy = fmaxf(rby - lty, 0.0f);
                    float inter = wx * wy;
                    float aa = (pl[pi][2] - pl[pi][0]) * (pl[pi][3] - pl[pi][1]);
                    float ab = (gl[gi][2] - gl[gi][0]) * (gl[gi][3] - gl[gi][1]);
                    iou[pi][gi] = __fdividef(inter, aa + ab - inter + 1e-7f);
                }
            }

            // argmax over pi (first index wins ties, matching jnp.argmax)
            int ind0 = (iou[1][0] > iou[0][0]) ? 1 : 0;
            int ind1 = (iou[1][1] > iou[0][1]) ? 1 : 0;

            bool same_g = (gbox[0][0] == gbox[1][0]) && (gbox[0][1] == gbox[1][1]) &&
                          (gbox[0][2] == gbox[1][2]) && (gbox[0][3] == gbox[1][3]);
            bool same_ind = (ind0 == ind1);

            float box_cell;
            if (same_g) {
                box_cell = box_loss_f(poff[ind0], gbox[0]);
            } else if (same_ind) {
                box_cell = box_loss_f(poff[0], gbox[0]) + box_loss_f(poff[1], gbox[1]);
            } else {
                box_cell = box_loss_f(poff[ind0], gbox[0]) + box_loss_f(poff[ind1], gbox[1]);
            }

            float pc0 = pv[IS], pc1 = pv[IS + 1];
            float conf_cell = same_g ? bce_f(ind1 ? pc1 : pc0, 1.0f)
                                     : (bce_f(pc0, 1.0f) + bce_f(pc1, 1.0f));

            acc = L_BOX * box_cell + conf_cell + cls;
        } else {
            // negative cell: 0.5 * (bce(pc0,0)+bce(pc1,0))
            float negc = bce_f(pv[IS], 0.0f) + bce_f(pv[IS + 1], 0.0f);
            acc = L_NEG * negc;
        }
    }

    // ---- deterministic block reduction (4 warps) ----
    #pragma unroll
    for (int o = 16; o > 0; o >>= 1)
        acc += __shfl_down_sync(0xffffffffu, acc, o);

    __shared__ float warp_sums[TPB / 32];
    int lane = tid & 31;
    int wid  = tid >> 5;
    if (lane == 0) warp_sums[wid] = acc;
    __syncthreads();

    if (tid == 0) {
        float v = warp_sums[0] + warp_sums[1] + warp_sums[2] + warp_sums[3];
        g_partials[blockIdx.x] = (double)v;
    }

    // ---- last-block finalization (deterministic fixed-order sum) ----
    __shared__ bool isLast;
    if (tid == 0) {
        __threadfence();
        unsigned int v = atomicAdd(&g_count, 1u);
        isLast = (v == gridDim.x - 1);
    }
    __syncthreads();

    if (isLast) {
        __shared__ double sh[TPB];
        double s = 0.0;
        for (int i = tid; i < (int)gridDim.x; i += TPB)
            s += g_partials[i];
        sh[tid] = s;
        __syncthreads();
        #pragma unroll
        for (int stride = TPB / 2; stride > 0; stride >>= 1) {
            if (tid < stride) sh[tid] += sh[tid + stride];
            __syncthreads();
        }
        if (tid == 0) {
            out[0] = (float)(sh[0] * (double)inv_nb);
            g_count = 0;   // reset for next (graph-replayed) launch
        }
    }
}

extern "C" void kernel_launch(void* const* d_in, const int* in_sizes, int n_in,
                              void* d_out, int out_size) {
    const float* p = (const float*)d_in[0];
    const float* g = (const float*)d_in[1];
    float* out = (float*)d_out;

    int ncells = in_sizes[0] / DCH;                 // B * 49
    int batch  = ncells / (GRID_N * GRID_N);        // B
    int nblocks = (ncells + TPB - 1) / TPB;

    yolo_loss_kernel<<<nblocks, TPB>>>(p, g, ncells, out, 1.0f / (float)batch);
}

// round 4
// speedup vs baseline: 1.2918x; 1.2649x over previous
#include <cuda_runtime.h>

#define GRID_N   7
#define NB       2
#define NC       20
#define IS       8
#define DCH      30
#define L_BOX    5.0f
#define L_NEG    0.5f

#define TPB      256
#define MAX_BLOCKS 8192

__device__ double g_partials[MAX_BLOCKS];
__device__ unsigned int g_count = 0;

__device__ __forceinline__ float bce_f(float x, float t) {
    // max(x,0) - x*t + log1p(exp(-|x|)), fast-math version
    return fmaxf(x, 0.0f) - x * t + __logf(1.0f + __expf(-fabsf(x)));
}

__device__ __forceinline__ float box_loss_f(const float* pb, const float* gb) {
    float dx = pb[0] - gb[0];
    float dy = pb[1] - gb[1];
    float sw = sqrtf(fabsf(pb[2])) - sqrtf(gb[2]);
    float sh = sqrtf(fabsf(pb[3])) - sqrtf(gb[3]);
    return dx * dx + dy * dy + sw * sw + sh * sh;
}

__global__ void __launch_bounds__(TPB)
yolo_loss_kernel(const float* __restrict__ p, const float* __restrict__ g,
                 int ncells, float* __restrict__ out, float inv_nb) {
    const int tid = threadIdx.x;
    const int idx = blockIdx.x * TPB + tid;
    float acc = 0.0f;

    if (idx < ncells) {
        const float* pc = p + (size_t)idx * DCH;
        const float* gc = g + (size_t)idx * DCH;

        // ---- always needed: predicted conf pair + ground-truth conf ----
        float2 pconf = *reinterpret_cast<const float2*>(pc + IS);   // p[8], p[9]
        float  conf_g = __ldg(gc + IS);                              // g[8]

        if (conf_g > 0.0f) {
            // ================= positive cell =================
            // box parts: p[0..7], g[0..7] via float2
            float pv[IS], gv[IS];
            const float2* pb2 = reinterpret_cast<const float2*>(pc);
            const float2* gb2 = reinterpret_cast<const float2*>(gc);
            #pragma unroll
            for (int i = 0; i < IS / 2; i++) {
                float2 a = pb2[i]; pv[2 * i] = a.x; pv[2 * i + 1] = a.y;
                float2 b = gb2[i]; gv[2 * i] = b.x; gv[2 * i + 1] = b.y;
            }

            // ---- classification: streaming accumulate over 10 float2 pairs ----
            float cls = 0.0f;
            const float2* pcl2 = reinterpret_cast<const float2*>(pc + NB * 5);
            const float2* gcl2 = reinterpret_cast<const float2*>(gc + NB * 5);
            #pragma unroll
            for (int i = 0; i < NC / 2; i++) {
                float2 a = pcl2[i];
                float2 b = gcl2[i];
                cls += bce_f(a.x, b.x) + bce_f(a.y, b.y);
            }

            // ---- cell coordinates: cr = (col, row) ----
            int cell = idx % (GRID_N * GRID_N);
            float col = (float)(cell % GRID_N);
            float row = (float)(cell / GRID_N);

            // ---- box offsets ----
            float poff[NB][4], gbox[NB][4];
            #pragma unroll
            for (int b = 0; b < NB; b++) {
                poff[b][0] = __fdividef(1.0f, 1.0f + __expf(-pv[4 * b + 0]));
                poff[b][1] = __fdividef(1.0f, 1.0f + __expf(-pv[4 * b + 1]));
                poff[b][2] = pv[4 * b + 2];
                poff[b][3] = pv[4 * b + 3];
                gbox[b][0] = gv[4 * b + 0];
                gbox[b][1] = gv[4 * b + 1];
                gbox[b][2] = gv[4 * b + 2];
                gbox[b][3] = gv[4 * b + 3];
            }

            // ---- ltrb boxes in image coords ----
            float pl[NB][4], gl[NB][4];
            #pragma unroll
            for (int b = 0; b < NB; b++) {
                float cx = (poff[b][0] + col) * (1.0f / GRID_N);
                float cy = (poff[b][1] + row) * (1.0f / GRID_N);
                float w  = poff[b][2], h = poff[b][3];
                pl[b][0] = cx - w * 0.5f; pl[b][1] = cy - h * 0.5f;
                pl[b][2] = cx + w * 0.5f; pl[b][3] = cy + h * 0.5f;
                float gx = (gbox[b][0] + col) * (1.0f / GRID_N);
                float gy = (gbox[b][1] + row) * (1.0f / GRID_N);
                float gw = gbox[b][2], gh = gbox[b][3];
                gl[b][0] = gx - gw * 0.5f; gl[b][1] = gy - gh * 0.5f;
                gl[b][2] = gx + gw * 0.5f; gl[b][3] = gy + gh * 0.5f;
            }

            // ---- 2x2 IoU matrix: iou[pi][gi] ----
            float iou[NB][NB];
            #pragma unroll
            for (int pi = 0; pi < NB; pi++) {
                #pragma unroll
                for (int gi = 0; gi < NB; gi++) {
                    float ltx = fmaxf(pl[pi][0], gl[gi][0]);
                    float lty = fmaxf(pl[pi][1], gl[gi][1]);
                    float rbx = fminf(pl[pi][2], gl[gi][2]);
                    float rby = fminf(pl[pi][3], gl[gi][3]);
                    float wx = fmaxf(rbx - ltx, 0.0f);
                    float wy = fmaxf(rby - lty, 0.0f);
                    float inter = wx * wy;
                    float aa = (pl[pi][2] - pl[pi][0]) * (pl[pi][3] - pl[pi][1]);
                    float ab = (gl[gi][2] - gl[gi][0]) * (gl[gi][3] - gl[gi][1]);
                    iou[pi][gi] = __fdividef(inter, aa + ab - inter + 1e-7f);
                }
            }

            // argmax over pi (first index wins ties, matching jnp.argmax)
            int ind0 = (iou[1][0] > iou[0][0]) ? 1 : 0;
            int ind1 = (iou[1][1] > iou[0][1]) ? 1 : 0;

            bool same_g = (gbox[0][0] == gbox[1][0]) && (gbox[0][1] == gbox[1][1]) &&
                          (gbox[0][2] == gbox[1][2]) && (gbox[0][3] == gbox[1][3]);
            bool same_ind = (ind0 == ind1);

            float box_cell;
            if (same_g) {
                box_cell = box_loss_f(poff[ind0], gbox[0]);
            } else if (same_ind) {
                box_cell = box_loss_f(poff[0], gbox[0]) + box_loss_f(poff[1], gbox[1]);
            } else {
                box_cell = box_loss_f(poff[ind0], gbox[0]) + box_loss_f(poff[ind1], gbox[1]);
            }

            float conf_cell = same_g ? bce_f(ind1 ? pconf.y : pconf.x, 1.0f)
                                     : (bce_f(pconf.x, 1.0f) + bce_f(pconf.y, 1.0f));

            acc = L_BOX * box_cell + conf_cell + cls;
        } else {
            // ================= negative cell =================
            float negc = bce_f(pconf.x, 0.0f) + bce_f(pconf.y, 0.0f);
            acc = L_NEG * negc;
        }
    }

    // ---- deterministic block reduction (8 warps) ----
    #pragma unroll
    for (int o = 16; o > 0; o >>= 1)
        acc += __shfl_down_sync(0xffffffffu, acc, o);

    __shared__ float warp_sums[TPB / 32];
    int lane = tid & 31;
    int wid  = tid >> 5;
    if (lane == 0) warp_sums[wid] = acc;
    __syncthreads();

    if (tid == 0) {
        float v = 0.0f;
        #pragma unroll
        for (int w = 0; w < TPB / 32; w++) v += warp_sums[w];
        g_partials[blockIdx.x] = (double)v;
    }

    // ---- last-block finalization (deterministic fixed-order sum) ----
    __shared__ bool isLast;
    if (tid == 0) {
        __threadfence();
        unsigned int v = atomicAdd(&g_count, 1u);
        isLast = (v == gridDim.x - 1);
    }
    __syncthreads();

    if (isLast) {
        __shared__ double sh[TPB];
        double s = 0.0;
        for (int i = tid; i < (int)gridDim.x; i += TPB)
            s += g_partials[i];
        sh[tid] = s;
        __syncthreads();
        #pragma unroll
        for (int stride = TPB / 2; stride > 0; stride >>= 1) {
            if (tid < stride) sh[tid] += sh[tid + stride];
            __syncthreads();
        }
        if (tid == 0) {
            out[0] = (float)(sh[0] * (double)inv_nb);
            g_count = 0;   // reset for next (graph-replayed) launch
        }
    }
}

extern "C" void kernel_launch(void* const* d_in, const int* in_sizes, int n_in,
                              void* d_out, int out_size) {
    const float* p = (const float*)d_in[0];
    const float* g = (const float*)d_in[1];
    float* out = (float*)d_out;

    int ncells = in_sizes[0] / DCH;                 // B * 49
    int batch  = ncells / (GRID_N * GRID_N);        // B
    int nblocks = (ncells + TPB - 1) / TPB;

    yolo_loss_kernel<<<nblocks, TPB>>>(p, g, ncells, out, 1.0f / (float)batch);
}